// round 15
// baseline (speedup 1.0000x reference)
#include <cuda_runtime.h>

#define UNITS  224
#define SENS   64
#define MOTORN 32
#define CMDN   64
#define INTERN 128
#define OUTL   32
#define NB     32
#define NT     32
#define UNF    6
#define CAPS   32
#define CAPI   64
#define CAPC   16
#define CAPM   32
#define NBLK   592
#define NTH    256
#define LOG2E  1.4426950408889634f
#define EPSF   1e-8f

// ---------------- compacted tables (rebuilt every launch) ----------------
__device__ float4 g_ssyn [UNITS * CAPS];   // ex2 form {s*log2e, s*mu*log2e, wm, wm*erev}
__device__ int    g_sidx [UNITS * CAPS];
__device__ int    g_scnt [UNITS];
__device__ float4 g_cisyn[CMDN * CAPI];    // ex2 form
__device__ int    g_ciix [CMDN * CAPI];
__device__ int    g_cic  [CMDN];
__device__ float4 g_ccsyn[CMDN * CAPC];    // tanh form {.5s, .5s*mu, .5wm, .5wm*erev}
__device__ int    g_ccix [CMDN * CAPC];
__device__ int    g_ccc  [CMDN];
__device__ float2 g_ccb  [CMDN];           // {sum .5wm*erev, sum .5wm}
__device__ float4 g_msyn [MOTORN * CAPM];  // ex2 form
__device__ int    g_mtix [MOTORN * CAPM];
__device__ int    g_mc   [MOTORN];
__device__ int    g_badv [UNITS];

// ---------------- scratch ----------------
__device__ float2 g_ssum [NB * NT * 96];
__device__ float2 g_iac  [NB * NT * INTERN];
__device__ float  g_vtraj[NB * NT * UNF * INTERN];
__device__ float2 g_pcmd [NB * NT * UNF * CMDN];
__device__ float  g_ctraj[NB * NT * UNF * CMDN];
__device__ float2 g_mac  [NB * NT * UNF * MOTORN];

// monotonic counters (never reset; replay-safe via g_runs epoch)
__device__ unsigned g_arrive;
__device__ unsigned g_runs;
__device__ unsigned g_done  [NB];   // P2 items per batch (32/run)
__device__ unsigned g_p3done[NB];   // 1/run
__device__ unsigned g_p4done[NB];   // 32/run

__device__ __forceinline__ float ex2f(float x) {
    float r; asm("ex2.approx.ftz.f32 %0, %1;" : "=f"(r) : "f"(x)); return r;
}
__device__ __forceinline__ float rcpf(float x) {
    float r; asm("rcp.approx.ftz.f32 %0, %1;" : "=f"(r) : "f"(x)); return r;
}
__device__ __forceinline__ float tanhf_a(float x) {
    float r; asm("tanh.approx.f32 %0, %1;" : "=f"(r) : "f"(x)); return r;
}
__device__ __forceinline__ void barn64() {
    asm volatile("bar.sync 1, 64;" ::: "memory");
}

// Poll with plain volatile loads (no RMW -> no L2 atomic-ALU serialization).
// Counters are monotonic, so stale reads only cause extra spins.
__device__ __forceinline__ void grid_barrier() {
    __syncthreads();
    if (threadIdx.x == 0) {
        __threadfence();
        unsigned old = atomicAdd(&g_arrive, 1u);
        unsigned target = (old / NBLK + 1u) * NBLK;
        while (*((volatile unsigned*)&g_arrive) < target) { __nanosleep(64); }
        __threadfence();
    }
    __syncthreads();
}
__device__ __forceinline__ void wait_ge(unsigned* ctr, unsigned target) {
    if (threadIdx.x == 0) {
        while (*((volatile unsigned*)ctr) < target) { __nanosleep(32); }
        __threadfence();
    }
    __syncthreads();
}
__device__ __forceinline__ void signal(unsigned* ctr) {
    __syncthreads();
    if (threadIdx.x == 0) { __threadfence(); atomicAdd(ctr, 1u); }
}

#define SMEM_BYTES 20992

__global__ void __launch_bounds__(NTH, 4)
kall(const float* __restrict__ inputs,
     const float* __restrict__ input_w, const float* __restrict__ input_b,
     const float* __restrict__ smu,  const float* __restrict__ ssig,
     const float* __restrict__ swt,  const float* __restrict__ serev,
     const float* __restrict__ smask,
     const float* __restrict__ mu,   const float* __restrict__ sig,
     const float* __restrict__ wt,   const float* __restrict__ erev,
     const float* __restrict__ mask,
     const float* __restrict__ gleak, const float* __restrict__ vleak,
     const float* __restrict__ cm,
     const float* __restrict__ output_w, const float* __restrict__ output_b,
     const float* __restrict__ dense_w,  const float* __restrict__ dense_b,
     float* __restrict__ out)
{
    __shared__ __align__(16) char smemu[SMEM_BYTES];
    const int bx = blockIdx.x;
    const int t  = threadIdx.x;
    const int wid = t >> 5;
    const int lane = t & 31;
    const unsigned FULL = 0xffffffffu;

    if (bx == 0 && t == 0) atomicAdd(&g_runs, 1u);

    // ================= P0: prep (one warp per post column; blocks 0..27) =====
    if (bx < 28) {
        const int j = bx * 8 + wid;
        const unsigned lt = (1u << lane) - 1u;
        int bad = 0;

        float mv[7];
#pragma unroll
        for (int r = 0; r < 7; r++) mv[r] = mask[(r * 32 + lane) * UNITS + j];
        float sv[2];
#pragma unroll
        for (int r = 0; r < 2; r++) sv[r] = smask[(r * 32 + lane) * UNITS + j];

        if (j < MOTORN) {
            int cnt = 0;
#pragma unroll
            for (int r = 0; r < 7; r++) {
                const int i = r * 32 + lane, gi = i * UNITS + j;
                const bool act = (mv[r] != 0.f);
                if (act && i < MOTORN) bad = 1;
                unsigned bal = __ballot_sync(FULL, act);
                if (act) {
                    int pos = cnt + __popc(bal & lt);
                    if (pos < CAPM && i >= MOTORN) {
                        float sg = sig[gi], wm = wt[gi] * mv[r];
                        g_msyn[j * CAPM + pos] =
                            make_float4(sg * LOG2E, sg * mu[gi] * LOG2E, wm, wm * erev[gi]);
                        g_mtix[j * CAPM + pos] = i - MOTORN;
                    }
                }
                cnt += __popc(bal);
            }
            if (cnt > CAPM) bad = 1;
            if (lane == 0) g_mc[j] = cnt;
        } else if (j < MOTORN + CMDN) {
            const int c = j - MOTORN;
            int icnt = 0, ccnt = 0;
#pragma unroll
            for (int r = 0; r < 7; r++) {
                const int i = r * 32 + lane, gi = i * UNITS + j;
                const bool act = (mv[r] != 0.f);
                if (act && i < MOTORN) bad = 1;
                const bool isI = act && (i >= MOTORN + CMDN);
                const bool isC = act && (i >= MOTORN) && (i < MOTORN + CMDN);
                unsigned balI = __ballot_sync(FULL, isI);
                unsigned balC = __ballot_sync(FULL, isC);
                if (isI) {
                    int pos = icnt + __popc(balI & lt);
                    if (pos < CAPI) {
                        float sg = sig[gi], wm = wt[gi] * mv[r];
                        g_cisyn[c * CAPI + pos] =
                            make_float4(sg * LOG2E, sg * mu[gi] * LOG2E, wm, wm * erev[gi]);
                        g_ciix[c * CAPI + pos] = i - (MOTORN + CMDN);
                    }
                }
                if (isC) {
                    int pos = ccnt + __popc(balC & lt);
                    if (pos < CAPC) {
                        float sg = sig[gi], wm = wt[gi] * mv[r];
                        g_ccsyn[c * CAPC + pos] =
                            make_float4(0.5f * sg, 0.5f * sg * mu[gi],
                                        0.5f * wm, 0.5f * wm * erev[gi]);
                        g_ccix[c * CAPC + pos] = i - MOTORN;
                    }
                }
                icnt += __popc(balI);
                ccnt += __popc(balC);
            }
            if (icnt > CAPI || ccnt > CAPC) bad = 1;
            for (int pos = ccnt + lane; pos < CAPC; pos += 32) {
                g_ccsyn[c * CAPC + pos] = make_float4(0.f, 0.f, 0.f, 0.f);
                g_ccix[c * CAPC + pos] = 0;
            }
            if (lane == 0) { g_cic[c] = icnt; g_ccc[c] = ccnt; }
            __syncwarp();
            float swre = 0.f, sw = 0.f;
            if (lane < CAPC) {
                float4 e = g_ccsyn[c * CAPC + lane];
                swre = e.w; sw = e.z;
            }
#pragma unroll
            for (int off = 16; off; off >>= 1) {
                swre += __shfl_xor_sync(FULL, swre, off);
                sw   += __shfl_xor_sync(FULL, sw, off);
            }
            if (lane == 0) g_ccb[c] = make_float2(swre, sw);
        } else {
#pragma unroll
            for (int r = 0; r < 7; r++)
                if (mv[r] != 0.f) bad = 1;
        }

        int cnt = 0;
#pragma unroll
        for (int r = 0; r < 2; r++) {
            const int i = r * 32 + lane, gi = i * UNITS + j;
            const bool act = (sv[r] != 0.f);
            unsigned bal = __ballot_sync(FULL, act);
            if (act) {
                int pos = cnt + __popc(bal & lt);
                if (pos < CAPS) {
                    float sg = ssig[gi], wm = swt[gi] * sv[r];
                    g_ssyn[j * CAPS + pos] =
                        make_float4(sg * LOG2E, sg * smu[gi] * LOG2E, wm, wm * serev[gi]);
                    g_sidx[j * CAPS + pos] = i;
                }
            }
            cnt += __popc(bal);
        }
        if (cnt > CAPS) bad = 1;
        if (lane == 0) g_scnt[j] = cnt;

        bad = (__ballot_sync(FULL, bad) != 0u);
        if (lane == 0) g_badv[j] = bad;
    }
    grid_barrier();   // #1
    const unsigned runs = g_runs;

    // ---- validity check (grid-uniform) ----
    {
        int badl = 0;
        for (int i = t; i < UNITS; i += NTH) badl |= g_badv[i];
        if (__syncthreads_or(badl)) {
            // ====== DENSE FALLBACK (blocks 0..31, any wiring); no flags used ==
            if (bx < NB) {
                float* v0s = (float*)smemu;
                float* v1s = v0s + UNITS;
                float* sxf = v1s + UNITS;
                const int b = bx, j = t;
                float cmt = 0.f, gl = 0.f, gv = 0.f;
                if (j < UNITS) {
                    cmt = cm[j] * (float)UNF; gl = gleak[j]; gv = gl * vleak[j];
                    v0s[j] = 0.f;
                }
                __syncthreads();
                float* cur = v0s; float* nxt = v1s;
                for (int s = 0; s < NT; s++) {
                    if (t < SENS)
                        sxf[t] = fmaf(inputs[(b * NT + s) * SENS + t], input_w[t], input_b[t]);
                    __syncthreads();
                    float sn = 0.f, sd = 0.f;
                    if (j < UNITS) {
                        for (int i = 0; i < SENS; i++) {
                            float m = smask[i * UNITS + j];
                            if (m != 0.f) {
                                float sg = ssig[i * UNITS + j];
                                float svv = rcpf(1.f + ex2f(LOG2E * sg * (smu[i * UNITS + j] - sxf[i])));
                                float wm = swt[i * UNITS + j] * m;
                                sd += wm * svv; sn += wm * serev[i * UNITS + j] * svv;
                            }
                        }
                    }
                    for (int u = 0; u < UNF; u++) {
                        float na = sn, da = sd;
                        if (j < UNITS) {
                            for (int i = 0; i < UNITS; i++) {
                                float m = mask[i * UNITS + j];
                                if (m != 0.f) {
                                    float sg = sig[i * UNITS + j];
                                    float svv = rcpf(1.f + ex2f(LOG2E * sg * (mu[i * UNITS + j] - cur[i])));
                                    float wm = wt[i * UNITS + j] * m;
                                    da += wm * svv; na += wm * erev[i * UNITS + j] * svv;
                                }
                            }
                            nxt[j] = (fmaf(cmt, cur[j], gv) + na) * rcpf(cmt + gl + da + EPSF);
                        }
                        __syncthreads();
                        float* tmp = cur; cur = nxt; nxt = tmp;
                    }
                    if (t < OUTL) {
                        float acc = dense_b[t];
                        for (int m = 0; m < MOTORN; m++)
                            acc = fmaf(fmaf(cur[m], output_w[m], output_b[m]),
                                       dense_w[m * OUTL + t], acc);
                        out[(b * NT + s) * OUTL + t] = acc;
                    }
                    __syncthreads();
                }
            }
            return;
        }
    }

    // ================= P1: sensory sums + inter affine coeffs =================
    {
        float* sx = (float*)smemu;
        const int scnt = (t < UNITS) ? min(g_scnt[t], CAPS) : 0;
        float cmt = 0.f, gl = 0.f, vl = 0.f;
        if (t < UNITS) { cmt = cm[t] * (float)UNF; gl = gleak[t]; vl = vleak[t]; }
        for (int bs = bx; bs < NB * NT; bs += NBLK) {
            if (t < SENS)
                sx[t] = fmaf(inputs[bs * SENS + t], input_w[t], input_b[t]);
            __syncthreads();
            if (t < UNITS) {
                float sn = 0.f, sd = 0.f;
#pragma unroll 4
                for (int k = 0; k < scnt; k++) {
                    float4 sy = g_ssyn[t * CAPS + k];
                    float x = sx[g_sidx[t * CAPS + k]];
                    float sg = rcpf(1.f + ex2f(fmaf(-sy.x, x, sy.y)));
                    sd = fmaf(sy.z, sg, sd); sn = fmaf(sy.w, sg, sn);
                }
                if (t < MOTORN + CMDN) {
                    g_ssum[bs * 96 + t] = make_float2(sn, sd);
                } else {
                    float dinv = rcpf(cmt + gl + sd + EPSF);
                    g_iac[bs * INTERN + (t - 96)] =
                        make_float2(cmt * dinv, fmaf(gl, vl, sn) * dinv);
                }
            }
            __syncthreads();
        }
    }
    grid_barrier();   // #2

    // ================= P1.5: inter affine scans (blocks 0..15) ================
    {
        const int gid = bx * NTH + t;
        if (gid < NB * INTERN) {
            const int b = gid >> 7, i = gid & 127;
            float v = 0.f;
            float2 ac = g_iac[(b * NT) * INTERN + i];
            for (int s = 0; s < NT; s++) {
                const int sn = (s + 1 < NT) ? s + 1 : s;
                float2 nac = g_iac[(b * NT + sn) * INTERN + i];
                const int base = ((b * NT + s) * UNF) * INTERN + i;
#pragma unroll
                for (int u = 0; u < UNF; u++) {
                    g_vtraj[base + u * INTERN] = v;
                    v = fmaf(ac.x, v, ac.y);
                }
                ac = nac;
            }
        }
    }
    grid_barrier();   // #3

    // ===== P2: cmd <- inter partials (all blocks, per-batch flags) ===========
    {
        float (*vr)[INTERN] = (float (*)[INTERN])smemu;
        const int c = t >> 2, h = t & 3;
        const int cnt = min(g_cic[c], CAPI);
        for (int bs = bx; bs < NB * NT; bs += NBLK) {
            for (int i = t; i < UNF * INTERN; i += NTH)
                vr[i >> 7][i & 127] = g_vtraj[bs * (UNF * INTERN) + i];
            __syncthreads();
            float na[UNF], da[UNF];
#pragma unroll
            for (int u = 0; u < UNF; u++) { na[u] = 0.f; da[u] = 0.f; }
#pragma unroll 2
            for (int k = h; k < cnt; k += 4) {
                float4 sy = g_cisyn[c * CAPI + k];
                const int ix = g_ciix[c * CAPI + k];
#pragma unroll
                for (int u = 0; u < UNF; u++) {
                    float vp = vr[u][ix];
                    float sg = rcpf(1.f + ex2f(fmaf(-sy.x, vp, sy.y)));
                    da[u] = fmaf(sy.z, sg, da[u]);
                    na[u] = fmaf(sy.w, sg, na[u]);
                }
            }
#pragma unroll
            for (int u = 0; u < UNF; u++) {
                float nu = na[u], du = da[u];
                nu += __shfl_xor_sync(FULL, nu, 1);
                nu += __shfl_xor_sync(FULL, nu, 2);
                du += __shfl_xor_sync(FULL, du, 1);
                du += __shfl_xor_sync(FULL, du, 2);
                if (h == 0) g_pcmd[(bs * UNF + u) * CMDN + c] = make_float2(nu, du);
            }
            signal(&g_done[bs >> 5]);   // syncthreads + fence + add
        }
    }

    if (bx < NB) {
        // ===== P3: sequential command core for batch bx ======================
        float4* ssynS = (float4*)smemu;                 // [CAPC][CMDN] 16KB
        int*    sixS  = (int*)(smemu + 16384);          // [CAPC][CMDN] 4KB
        float*  vr0   = (float*)(smemu + 20480);        // 256B
        float*  vr1   = vr0 + CMDN;                     // 256B
        const int b = bx;
        for (int i = t; i < CMDN * CAPC; i += NTH) {
            const int p_ = i / CAPC, k_ = i % CAPC;     // transpose: [k][post]
            ssynS[k_ * CMDN + p_] = g_ccsyn[i];
            sixS [k_ * CMDN + p_] = g_ccix[i];
        }
        wait_ge(&g_done[b], runs * 32u);   // ends with __syncthreads (stages visible)

        if (t < CMDN) {
            const int p = t;
            const int j = MOTORN + p;
            const float cmt = cm[j] * (float)UNF;
            const float gl  = gleak[j];
            const float gv  = gl * vleak[j];
            const int   cnt = min(g_ccc[p], CAPC);
            const float2 cb = g_ccb[p];

            float v = 0.f;
            float* va = vr0; float* vb = vr1;
            va[p] = 0.f;
            float2 ss = g_ssum[(b * NT) * 96 + j];
            float2 pc[UNF];
#pragma unroll
            for (int u = 0; u < UNF; u++)
                pc[u] = g_pcmd[((b * NT) * UNF + u) * CMDN + p];
            barn64();

            for (int s = 0; s < NT; s++) {
                const int sn = (s + 1 < NT) ? s + 1 : s;
                float2 nss = g_ssum[(b * NT + sn) * 96 + j];
                float2 npc[UNF];
#pragma unroll
                for (int u = 0; u < UNF; u++)
                    npc[u] = g_pcmd[((b * NT + sn) * UNF + u) * CMDN + p];
                const float cn = gv + ss.x + cb.x;
                const float cd = cmt + gl + ss.y + cb.y + EPSF;
#pragma unroll
                for (int u = 0; u < UNF; u++) {
                    g_ctraj[((b * NT + s) * UNF + u) * CMDN + p] = v;
                    float na = 0.f, da = 0.f;
                    for (int k = 0; k < cnt; k++) {
                        float4 sy = ssynS[k * CMDN + p];
                        float vp = va[sixS[k * CMDN + p]];
                        float tt = tanhf_a(fmaf(sy.x, vp, -sy.y));
                        da = fmaf(sy.z, tt, da);
                        na = fmaf(sy.w, tt, na);
                    }
                    v = (fmaf(cmt, v, cn) + pc[u].x + na) * rcpf(cd + pc[u].y + da);
                    vb[p] = v;
                    barn64();
                    float* tmp = va; va = vb; vb = tmp;
                }
#pragma unroll
                for (int u = 0; u < UNF; u++) pc[u] = npc[u];
                ss = nss;
            }
        }
        signal(&g_p3done[b]);

        // ===== P5: motor scan + output GEMV for batch bx (warp 0) ============
        wait_ge(&g_p4done[b], runs * 32u);
        if (t < 32) {
            const int lane5 = t;
            const float ow = output_w[lane5], ob = output_b[lane5];
            const float db = dense_b[lane5];
            float dwc[32];
#pragma unroll
            for (int m = 0; m < 32; m++) dwc[m] = dense_w[m * OUTL + lane5];
            float v = 0.f;
            for (int s = 0; s < NT; s++) {
                const int bs = b * NT + s;
#pragma unroll
                for (int u = 0; u < UNF; u++) {
                    float2 ac = g_mac[(bs * UNF + u) * MOTORN + lane5];
                    v = fmaf(ac.x, v, ac.y);
                }
                float ym = fmaf(v, ow, ob);
                float acc = db;
#pragma unroll
                for (int m = 0; m < 32; m++)
                    acc = fmaf(__shfl_sync(FULL, ym, m), dwc[m], acc);
                out[bs * OUTL + lane5] = acc;
            }
        }
    } else {
        // ===== P4: motor affine coeffs (blocks 32..591, per-batch gated) =====
        float (*trow)[192] = (float (*)[192])smemu;
        const int m = t >> 3, h = t & 7;
        const int cnt = min(g_mc[m], CAPM);
        const float cmt = cm[m] * (float)UNF;
        const float gl = gleak[m], vl = vleak[m];
        for (int it = bx - NB; it < NB * NT; it += NBLK - NB) {
            wait_ge(&g_p3done[it >> 5], runs);
            for (int idx = t; idx < UNF * CMDN; idx += NTH) {
                int u = idx >> 6, c = idx & 63;
                trow[u][c] = g_ctraj[(it * UNF + u) * CMDN + c];
            }
            for (int idx = t; idx < UNF * INTERN; idx += NTH) {
                int u = idx >> 7, i = idx & 127;
                trow[u][CMDN + i] = g_vtraj[it * (UNF * INTERN) + idx];
            }
            __syncthreads();
            const float2 ssm = g_ssum[it * 96 + m];
            float na[UNF], da[UNF];
#pragma unroll
            for (int u = 0; u < UNF; u++) { na[u] = 0.f; da[u] = 0.f; }
            for (int k = h; k < cnt; k += 8) {
                float4 sy = g_msyn[m * CAPM + k];
                const int ix = g_mtix[m * CAPM + k];
#pragma unroll
                for (int u = 0; u < UNF; u++) {
                    float vp = trow[u][ix];
                    float sg = rcpf(1.f + ex2f(fmaf(-sy.x, vp, sy.y)));
                    da[u] = fmaf(sy.z, sg, da[u]);
                    na[u] = fmaf(sy.w, sg, na[u]);
                }
            }
#pragma unroll
            for (int u = 0; u < UNF; u++) {
                float nu = na[u], du = da[u];
                nu += __shfl_xor_sync(FULL, nu, 1);
                nu += __shfl_xor_sync(FULL, nu, 2);
                nu += __shfl_xor_sync(FULL, nu, 4);
                du += __shfl_xor_sync(FULL, du, 1);
                du += __shfl_xor_sync(FULL, du, 2);
                du += __shfl_xor_sync(FULL, du, 4);
                if (h == 0) {
                    float dinv = rcpf(cmt + gl + ssm.y + du + EPSF);
                    g_mac[(it * UNF + u) * MOTORN + m] =
                        make_float2(cmt * dinv, (fmaf(gl, vl, ssm.x) + nu) * dinv);
                }
            }
            signal(&g_p4done[it >> 5]);
        }
    }
}

extern "C" void kernel_launch(void* const* d_in, const int* in_sizes, int n_in,
                              void* d_out, int out_size)
{
    const float* inputs   = (const float*)d_in[0];
    const float* input_w  = (const float*)d_in[1];
    const float* input_b  = (const float*)d_in[2];
    const float* smu      = (const float*)d_in[3];
    const float* ssig     = (const float*)d_in[4];
    const float* swt      = (const float*)d_in[5];
    const float* serev    = (const float*)d_in[6];
    const float* smask    = (const float*)d_in[7];
    const float* mu       = (const float*)d_in[8];
    const float* sig      = (const float*)d_in[9];
    const float* wt       = (const float*)d_in[10];
    const float* erev     = (const float*)d_in[11];
    const float* mask     = (const float*)d_in[12];
    const float* gleak    = (const float*)d_in[13];
    const float* vleak    = (const float*)d_in[14];
    const float* cm       = (const float*)d_in[15];
    const float* output_w = (const float*)d_in[16];
    const float* output_b = (const float*)d_in[17];
    const float* dense_w  = (const float*)d_in[18];
    const float* dense_b  = (const float*)d_in[19];
    float* out = (float*)d_out;

    kall<<<NBLK, NTH>>>(inputs, input_w, input_b,
                        smu, ssig, swt, serev, smask,
                        mu, sig, wt, erev, mask,
                        gleak, vleak, cm,
                        output_w, output_b, dense_w, dense_b, out);
}

// round 16
// speedup vs baseline: 1.1377x; 1.1377x over previous
#include <cuda_runtime.h>

#define UNITS  224
#define SENS   64
#define MOTORN 32
#define CMDN   64
#define INTERN 128
#define OUTL   32
#define NB     32
#define NT     32
#define UNF    6
#define CAPS   32
#define CAPI   64
#define CAPC   16
#define CAPM   32
#define NBLK   444
#define NTH    256
#define LOG2E  1.4426950408889634f
#define EPSF   1e-8f

// ---------------- compacted tables (rebuilt every launch) ----------------
__device__ float4 g_ssyn [UNITS * CAPS];   // ex2 form {s*log2e, s*mu*log2e, wm, wm*erev}
__device__ int    g_sidx [UNITS * CAPS];
__device__ int    g_scnt [UNITS];
__device__ float4 g_cisyn[CMDN * CAPI];    // ex2 form
__device__ int    g_ciix [CMDN * CAPI];
__device__ int    g_cic  [CMDN];
__device__ float4 g_ccsyn[CMDN * CAPC];    // tanh form {.5s, .5s*mu, .5wm, .5wm*erev}
__device__ int    g_ccix [CMDN * CAPC];
__device__ int    g_ccc  [CMDN];
__device__ float2 g_ccb  [CMDN];           // {sum .5wm*erev, sum .5wm}
__device__ float4 g_msyn [MOTORN * CAPM];  // ex2 form
__device__ int    g_mtix [MOTORN * CAPM];
__device__ int    g_mc   [MOTORN];
__device__ int    g_badv [UNITS];

// ---------------- scratch ----------------
__device__ float2 g_ssum [NB * NT * 96];
__device__ float2 g_iac  [NB * NT * INTERN];
__device__ float  g_vtraj[NB * NT * UNF * INTERN];
__device__ float2 g_pcmd [NB * NT * UNF * CMDN];
__device__ float  g_ctraj[NB * NT * UNF * CMDN];
__device__ float2 g_mac  [NB * NT * UNF * MOTORN];

// monotonic grid-barrier counter (never reset; replay-safe)
__device__ unsigned g_arrive;

__device__ __forceinline__ float ex2f(float x) {
    float r; asm("ex2.approx.ftz.f32 %0, %1;" : "=f"(r) : "f"(x)); return r;
}
__device__ __forceinline__ float rcpf(float x) {
    float r; asm("rcp.approx.ftz.f32 %0, %1;" : "=f"(r) : "f"(x)); return r;
}
__device__ __forceinline__ float tanhf_a(float x) {
    float r; asm("tanh.approx.f32 %0, %1;" : "=f"(r) : "f"(x)); return r;
}
__device__ __forceinline__ void barn64() {
    asm volatile("bar.sync 1, 64;" ::: "memory");
}

__device__ __forceinline__ void grid_barrier() {
    __syncthreads();
    if (threadIdx.x == 0) {
        __threadfence();
        unsigned old = atomicAdd(&g_arrive, 1u);
        unsigned target = (old / NBLK + 1u) * NBLK;
        while (atomicAdd(&g_arrive, 0u) < target) { __nanosleep(64); }
        __threadfence();
    }
    __syncthreads();
}

// shared-memory union sizing (P3 tables dominate)
#define SMEM_BYTES 20992

__global__ void __launch_bounds__(NTH, 3)
kall(const float* __restrict__ inputs,
     const float* __restrict__ input_w, const float* __restrict__ input_b,
     const float* __restrict__ smu,  const float* __restrict__ ssig,
     const float* __restrict__ swt,  const float* __restrict__ serev,
     const float* __restrict__ smask,
     const float* __restrict__ mu,   const float* __restrict__ sig,
     const float* __restrict__ wt,   const float* __restrict__ erev,
     const float* __restrict__ mask,
     const float* __restrict__ gleak, const float* __restrict__ vleak,
     const float* __restrict__ cm,
     const float* __restrict__ output_w, const float* __restrict__ output_b,
     const float* __restrict__ dense_w,  const float* __restrict__ dense_b,
     float* __restrict__ out)
{
    __shared__ __align__(16) char smemu[SMEM_BYTES];
    const int bx = blockIdx.x;
    const int t  = threadIdx.x;
    const int wid = t >> 5;
    const int lane = t & 31;
    const unsigned FULL = 0xffffffffu;

    // ================= P0: prep (one warp per post column; blocks 0..27) =====
    if (bx < 28) {
        const int j = bx * 8 + wid;   // 28*8 = 224 warps, j in [0,224)
        const unsigned lt = (1u << lane) - 1u;
        int bad = 0;

        float mv[7];
#pragma unroll
        for (int r = 0; r < 7; r++) mv[r] = mask[(r * 32 + lane) * UNITS + j];
        float sv[2];
#pragma unroll
        for (int r = 0; r < 2; r++) sv[r] = smask[(r * 32 + lane) * UNITS + j];

        if (j < MOTORN) {
            int cnt = 0;
#pragma unroll
            for (int r = 0; r < 7; r++) {
                const int i = r * 32 + lane, gi = i * UNITS + j;
                const bool act = (mv[r] != 0.f);
                if (act && i < MOTORN) bad = 1;
                unsigned bal = __ballot_sync(FULL, act);
                if (act) {
                    int pos = cnt + __popc(bal & lt);
                    if (pos < CAPM && i >= MOTORN) {
                        float sg = sig[gi], wm = wt[gi] * mv[r];
                        g_msyn[j * CAPM + pos] =
                            make_float4(sg * LOG2E, sg * mu[gi] * LOG2E, wm, wm * erev[gi]);
                        g_mtix[j * CAPM + pos] = i - MOTORN;
                    }
                }
                cnt += __popc(bal);
            }
            if (cnt > CAPM) bad = 1;
            if (lane == 0) g_mc[j] = cnt;
        } else if (j < MOTORN + CMDN) {
            const int c = j - MOTORN;
            int icnt = 0, ccnt = 0;
#pragma unroll
            for (int r = 0; r < 7; r++) {
                const int i = r * 32 + lane, gi = i * UNITS + j;
                const bool act = (mv[r] != 0.f);
                if (act && i < MOTORN) bad = 1;
                const bool isI = act && (i >= MOTORN + CMDN);
                const bool isC = act && (i >= MOTORN) && (i < MOTORN + CMDN);
                unsigned balI = __ballot_sync(FULL, isI);
                unsigned balC = __ballot_sync(FULL, isC);
                if (isI) {
                    int pos = icnt + __popc(balI & lt);
                    if (pos < CAPI) {
                        float sg = sig[gi], wm = wt[gi] * mv[r];
                        g_cisyn[c * CAPI + pos] =
                            make_float4(sg * LOG2E, sg * mu[gi] * LOG2E, wm, wm * erev[gi]);
                        g_ciix[c * CAPI + pos] = i - (MOTORN + CMDN);
                    }
                }
                if (isC) {
                    int pos = ccnt + __popc(balC & lt);
                    if (pos < CAPC) {
                        float sg = sig[gi], wm = wt[gi] * mv[r];
                        g_ccsyn[c * CAPC + pos] =
                            make_float4(0.5f * sg, 0.5f * sg * mu[gi],
                                        0.5f * wm, 0.5f * wm * erev[gi]);
                        g_ccix[c * CAPC + pos] = i - MOTORN;
                    }
                }
                icnt += __popc(balI);
                ccnt += __popc(balC);
            }
            if (icnt > CAPI || ccnt > CAPC) bad = 1;
            for (int pos = ccnt + lane; pos < CAPC; pos += 32) {
                g_ccsyn[c * CAPC + pos] = make_float4(0.f, 0.f, 0.f, 0.f);
                g_ccix[c * CAPC + pos] = 0;
            }
            if (lane == 0) { g_cic[c] = icnt; g_ccc[c] = ccnt; }
            __syncwarp();
            float swre = 0.f, sw = 0.f;
            if (lane < CAPC) {
                float4 e = g_ccsyn[c * CAPC + lane];
                swre = e.w; sw = e.z;
            }
#pragma unroll
            for (int off = 16; off; off >>= 1) {
                swre += __shfl_xor_sync(FULL, swre, off);
                sw   += __shfl_xor_sync(FULL, sw, off);
            }
            if (lane == 0) g_ccb[c] = make_float2(swre, sw);
        } else {
#pragma unroll
            for (int r = 0; r < 7; r++)
                if (mv[r] != 0.f) bad = 1;   // inter posts must be recurrent-free
        }

        int cnt = 0;
#pragma unroll
        for (int r = 0; r < 2; r++) {
            const int i = r * 32 + lane, gi = i * UNITS + j;
            const bool act = (sv[r] != 0.f);
            unsigned bal = __ballot_sync(FULL, act);
            if (act) {
                int pos = cnt + __popc(bal & lt);
                if (pos < CAPS) {
                    float sg = ssig[gi], wm = swt[gi] * sv[r];
                    g_ssyn[j * CAPS + pos] =
                        make_float4(sg * LOG2E, sg * smu[gi] * LOG2E, wm, wm * serev[gi]);
                    g_sidx[j * CAPS + pos] = i;
                }
            }
            cnt += __popc(bal);
        }
        if (cnt > CAPS) bad = 1;
        if (lane == 0) g_scnt[j] = cnt;

        bad = (__ballot_sync(FULL, bad) != 0u);
        if (lane == 0) g_badv[j] = bad;
    }
    grid_barrier();   // #1

    // ---- validity check (grid-uniform) ----
    {
        int badl = 0;
        for (int i = t; i < UNITS; i += NTH) badl |= g_badv[i];
        if (__syncthreads_or(badl)) {
            // ====== DENSE FALLBACK (blocks 0..31, any wiring); no more barriers
            if (bx < NB) {
                float* v0s = (float*)smemu;
                float* v1s = v0s + UNITS;
                float* sxf = v1s + UNITS;
                const int b = bx, j = t;
                float cmt = 0.f, gl = 0.f, gv = 0.f;
                if (j < UNITS) {
                    cmt = cm[j] * (float)UNF; gl = gleak[j]; gv = gl * vleak[j];
                    v0s[j] = 0.f;
                }
                __syncthreads();
                float* cur = v0s; float* nxt = v1s;
                for (int s = 0; s < NT; s++) {
                    if (t < SENS)
                        sxf[t] = fmaf(inputs[(b * NT + s) * SENS + t], input_w[t], input_b[t]);
                    __syncthreads();
                    float sn = 0.f, sd = 0.f;
                    if (j < UNITS) {
                        for (int i = 0; i < SENS; i++) {
                            float m = smask[i * UNITS + j];
                            if (m != 0.f) {
                                float sg = ssig[i * UNITS + j];
                                float svv = rcpf(1.f + ex2f(LOG2E * sg * (smu[i * UNITS + j] - sxf[i])));
                                float wm = swt[i * UNITS + j] * m;
                                sd += wm * svv; sn += wm * serev[i * UNITS + j] * svv;
                            }
                        }
                    }
                    for (int u = 0; u < UNF; u++) {
                        float na = sn, da = sd;
                        if (j < UNITS) {
                            for (int i = 0; i < UNITS; i++) {
                                float m = mask[i * UNITS + j];
                                if (m != 0.f) {
                                    float sg = sig[i * UNITS + j];
                                    float svv = rcpf(1.f + ex2f(LOG2E * sg * (mu[i * UNITS + j] - cur[i])));
                                    float wm = wt[i * UNITS + j] * m;
                                    da += wm * svv; na += wm * erev[i * UNITS + j] * svv;
                                }
                            }
                            nxt[j] = (fmaf(cmt, cur[j], gv) + na) * rcpf(cmt + gl + da + EPSF);
                        }
                        __syncthreads();
                        float* tmp = cur; cur = nxt; nxt = tmp;
                    }
                    if (t < OUTL) {
                        float acc = dense_b[t];
                        for (int m = 0; m < MOTORN; m++)
                            acc = fmaf(fmaf(cur[m], output_w[m], output_b[m]),
                                       dense_w[m * OUTL + t], acc);
                        out[(b * NT + s) * OUTL + t] = acc;
                    }
                    __syncthreads();
                }
            }
            return;
        }
    }

    // ================= P1: sensory sums + inter affine coeffs =================
    {
        float* sx = (float*)smemu;
        const int scnt = (t < UNITS) ? min(g_scnt[t], CAPS) : 0;
        float cmt = 0.f, gl = 0.f, vl = 0.f;
        if (t < UNITS) { cmt = cm[t] * (float)UNF; gl = gleak[t]; vl = vleak[t]; }
        for (int bs = bx; bs < NB * NT; bs += NBLK) {
            if (t < SENS)
                sx[t] = fmaf(inputs[bs * SENS + t], input_w[t], input_b[t]);
            __syncthreads();
            if (t < UNITS) {
                float sn = 0.f, sd = 0.f;
#pragma unroll 4
                for (int k = 0; k < scnt; k++) {
                    float4 sy = g_ssyn[t * CAPS + k];
                    float x = sx[g_sidx[t * CAPS + k]];
                    float sg = rcpf(1.f + ex2f(fmaf(-sy.x, x, sy.y)));
                    sd = fmaf(sy.z, sg, sd); sn = fmaf(sy.w, sg, sn);
                }
                if (t < MOTORN + CMDN) {
                    g_ssum[bs * 96 + t] = make_float2(sn, sd);
                } else {
                    float dinv = rcpf(cmt + gl + sd + EPSF);
                    g_iac[bs * INTERN + (t - 96)] =
                        make_float2(cmt * dinv, fmaf(gl, vl, sn) * dinv);
                }
            }
            __syncthreads();
        }
    }
    grid_barrier();   // #2

    // ================= P1.5: inter affine scans (blocks 0..15) ================
    {
        const int gid = bx * NTH + t;
        if (gid < NB * INTERN) {
            const int b = gid >> 7, i = gid & 127;
            float v = 0.f;
            float2 ac = g_iac[(b * NT) * INTERN + i];
            for (int s = 0; s < NT; s++) {
                const int sn = (s + 1 < NT) ? s + 1 : s;
                float2 nac = g_iac[(b * NT + sn) * INTERN + i];
                const int base = ((b * NT + s) * UNF) * INTERN + i;
#pragma unroll
                for (int u = 0; u < UNF; u++) {
                    g_vtraj[base + u * INTERN] = v;
                    v = fmaf(ac.x, v, ac.y);
                }
                ac = nac;
            }
        }
    }
    grid_barrier();   // #3

    // ================= P2: cmd <- inter partials, k-outer =====================
    {
        float (*vr)[INTERN] = (float (*)[INTERN])smemu;
        const int c = t >> 2, h = t & 3;
        const int cnt = min(g_cic[c], CAPI);
        for (int bs = bx; bs < NB * NT; bs += NBLK) {
            for (int i = t; i < UNF * INTERN; i += NTH)
                vr[i >> 7][i & 127] = g_vtraj[bs * (UNF * INTERN) + i];
            __syncthreads();
            float na[UNF], da[UNF];
#pragma unroll
            for (int u = 0; u < UNF; u++) { na[u] = 0.f; da[u] = 0.f; }
#pragma unroll 2
            for (int k = h; k < cnt; k += 4) {
                float4 sy = g_cisyn[c * CAPI + k];
                const int ix = g_ciix[c * CAPI + k];
#pragma unroll
                for (int u = 0; u < UNF; u++) {
                    float vp = vr[u][ix];
                    float sg = rcpf(1.f + ex2f(fmaf(-sy.x, vp, sy.y)));
                    da[u] = fmaf(sy.z, sg, da[u]);
                    na[u] = fmaf(sy.w, sg, na[u]);
                }
            }
#pragma unroll
            for (int u = 0; u < UNF; u++) {
                float nu = na[u], du = da[u];
                nu += __shfl_xor_sync(FULL, nu, 1);
                nu += __shfl_xor_sync(FULL, nu, 2);
                du += __shfl_xor_sync(FULL, du, 1);
                du += __shfl_xor_sync(FULL, du, 2);
                if (h == 0) g_pcmd[(bs * UNF + u) * CMDN + c] = make_float2(nu, du);
            }
            __syncthreads();
        }
    }
    grid_barrier();   // #4

    // ===== P3: sequential command core (blocks 0..31), conflict-free tables ===
    if (bx < NB) {
        float4* ssynS = (float4*)smemu;                 // [CAPC][CMDN] 16KB (transposed)
        int*    sixS  = (int*)(smemu + 16384);          // [CAPC][CMDN] 4KB
        float*  vr0   = (float*)(smemu + 20480);        // 256B
        float*  vr1   = vr0 + CMDN;                     // (uses tail of union + slack)
        const int b = bx;
        for (int i = t; i < CMDN * CAPC; i += NTH) {
            const int p_ = i / CAPC, k_ = i % CAPC;     // transpose: [k][post]
            ssynS[k_ * CMDN + p_] = g_ccsyn[i];
            sixS [k_ * CMDN + p_] = g_ccix[i];
        }
        __syncthreads();
        if (t < CMDN) {
            const int p = t;
            const int j = MOTORN + p;
            const float cmt = cm[j] * (float)UNF;
            const float gl  = gleak[j];
            const float gv  = gl * vleak[j];
            const int   cnt = min(g_ccc[p], CAPC);
            const float2 cb = g_ccb[p];

            float v = 0.f;
            float* va = vr0; float* vb = vr1;
            va[p] = 0.f;
            float2 ss = g_ssum[(b * NT) * 96 + j];
            float2 pc[UNF];
#pragma unroll
            for (int u = 0; u < UNF; u++)
                pc[u] = g_pcmd[((b * NT) * UNF + u) * CMDN + p];
            barn64();

            for (int s = 0; s < NT; s++) {
                const int sn = (s + 1 < NT) ? s + 1 : s;
                float2 nss = g_ssum[(b * NT + sn) * 96 + j];
                float2 npc[UNF];
#pragma unroll
                for (int u = 0; u < UNF; u++)
                    npc[u] = g_pcmd[((b * NT + sn) * UNF + u) * CMDN + p];
                const float cn = gv + ss.x + cb.x;
                const float cd = cmt + gl + ss.y + cb.y + EPSF;
#pragma unroll
                for (int u = 0; u < UNF; u++) {
                    g_ctraj[((b * NT + s) * UNF + u) * CMDN + p] = v;
                    float na = 0.f, da = 0.f;
                    for (int k = 0; k < cnt; k++) {
                        float4 sy = ssynS[k * CMDN + p];   // conflict-free across lanes
                        float vp = va[sixS[k * CMDN + p]];
                        float tt = tanhf_a(fmaf(sy.x, vp, -sy.y));
                        da = fmaf(sy.z, tt, da);
                        na = fmaf(sy.w, tt, na);
                    }
                    v = (fmaf(cmt, v, cn) + pc[u].x + na) * rcpf(cd + pc[u].y + da);
                    vb[p] = v;
                    barn64();                              // single barrier per unfold
                    float* tmp = va; va = vb; vb = tmp;
                }
#pragma unroll
                for (int u = 0; u < UNF; u++) pc[u] = npc[u];
                ss = nss;
            }
        }
    }
    grid_barrier();   // #5

    // ================= P4: motor affine coeffs, k-outer =======================
    {
        float (*trow)[192] = (float (*)[192])smemu;
        const int m = t >> 3, h = t & 7;
        const int cnt = min(g_mc[m], CAPM);
        const float cmt = cm[m] * (float)UNF;
        const float gl = gleak[m], vl = vleak[m];
        for (int bs = bx; bs < NB * NT; bs += NBLK) {
            for (int idx = t; idx < UNF * CMDN; idx += NTH) {
                int u = idx >> 6, c = idx & 63;
                trow[u][c] = g_ctraj[(bs * UNF + u) * CMDN + c];
            }
            for (int idx = t; idx < UNF * INTERN; idx += NTH) {
                int u = idx >> 7, i = idx & 127;
                trow[u][CMDN + i] = g_vtraj[bs * (UNF * INTERN) + idx];
            }
            __syncthreads();
            const float2 ssm = g_ssum[bs * 96 + m];
            float na[UNF], da[UNF];
#pragma unroll
            for (int u = 0; u < UNF; u++) { na[u] = 0.f; da[u] = 0.f; }
            for (int k = h; k < cnt; k += 8) {
                float4 sy = g_msyn[m * CAPM + k];
                const int ix = g_mtix[m * CAPM + k];
#pragma unroll
                for (int u = 0; u < UNF; u++) {
                    float vp = trow[u][ix];
                    float sg = rcpf(1.f + ex2f(fmaf(-sy.x, vp, sy.y)));
                    da[u] = fmaf(sy.z, sg, da[u]);
                    na[u] = fmaf(sy.w, sg, na[u]);
                }
            }
#pragma unroll
            for (int u = 0; u < UNF; u++) {
                float nu = na[u], du = da[u];
                nu += __shfl_xor_sync(FULL, nu, 1);
                nu += __shfl_xor_sync(FULL, nu, 2);
                nu += __shfl_xor_sync(FULL, nu, 4);
                du += __shfl_xor_sync(FULL, du, 1);
                du += __shfl_xor_sync(FULL, du, 2);
                du += __shfl_xor_sync(FULL, du, 4);
                if (h == 0) {
                    float dinv = rcpf(cmt + gl + ssm.y + du + EPSF);
                    g_mac[(bs * UNF + u) * MOTORN + m] =
                        make_float2(cmt * dinv, (fmaf(gl, vl, ssm.x) + nu) * dinv);
                }
            }
            __syncthreads();
        }
    }
    grid_barrier();   // #6

    // ================= P5: motor scans + output GEMV (blocks 0..7) ============
    if (bx < 8 && t < 128) {
        const int w = t >> 5, lane5 = t & 31;
        const int b = bx * 4 + w;
        const float ow = output_w[lane5], ob = output_b[lane5];
        const float db = dense_b[lane5];
        float dwc[32];
#pragma unroll
        for (int m = 0; m < 32; m++) dwc[m] = dense_w[m * OUTL + lane5];

        float v = 0.f;
        float2 mc[UNF];
#pragma unroll
        for (int u = 0; u < UNF; u++)
            mc[u] = g_mac[((b * NT) * UNF + u) * MOTORN + lane5];

        for (int s = 0; s < NT; s++) {
            const int sn = (s + 1 < NT) ? s + 1 : s;
            float2 nmc[UNF];
#pragma unroll
            for (int u = 0; u < UNF; u++)
                nmc[u] = g_mac[((b * NT + sn) * UNF + u) * MOTORN + lane5];
#pragma unroll
            for (int u = 0; u < UNF; u++) v = fmaf(mc[u].x, v, mc[u].y);
            float ym = fmaf(v, ow, ob);
            float acc = db;
#pragma unroll
            for (int m = 0; m < 32; m++)
                acc = fmaf(__shfl_sync(FULL, ym, m), dwc[m], acc);
            out[(b * NT + s) * OUTL + lane5] = acc;
#pragma unroll
            for (int u = 0; u < UNF; u++) mc[u] = nmc[u];
        }
    }
}

extern "C" void kernel_launch(void* const* d_in, const int* in_sizes, int n_in,
                              void* d_out, int out_size)
{
    const float* inputs   = (const float*)d_in[0];
    const float* input_w  = (const float*)d_in[1];
    const float* input_b  = (const float*)d_in[2];
    const float* smu      = (const float*)d_in[3];
    const float* ssig     = (const float*)d_in[4];
    const float* swt      = (const float*)d_in[5];
    const float* serev    = (const float*)d_in[6];
    const float* smask    = (const float*)d_in[7];
    const float* mu       = (const float*)d_in[8];
    const float* sig      = (const float*)d_in[9];
    const float* wt       = (const float*)d_in[10];
    const float* erev     = (const float*)d_in[11];
    const float* mask     = (const float*)d_in[12];
    const float* gleak    = (const float*)d_in[13];
    const float* vleak    = (const float*)d_in[14];
    const float* cm       = (const float*)d_in[15];
    const float* output_w = (const float*)d_in[16];
    const float* output_b = (const float*)d_in[17];
    const float* dense_w  = (const float*)d_in[18];
    const float* dense_b  = (const float*)d_in[19];
    float* out = (float*)d_out;

    kall<<<NBLK, NTH>>>(inputs, input_w, input_b,
                        smu, ssig, swt, serev, smask,
                        mu, sig, wt, erev, mask,
                        gleak, vleak, cm,
                        output_w, output_b, dense_w, dense_b, out);
}